// round 1
// baseline (speedup 1.0000x reference)
#include <cuda_runtime.h>
#include <cuda_bf16.h>
#include <math.h>

// Problem constants (PlanesweepCorrelation: N=2, C=64, S=32, H=128, W=160, G=8)
#define NN 2
#define CC 64
#define SS 32
#define HH 128
#define WW 160
#define HWSZ (HH * WW)          // 20480
#define NPIX (NN * HWSZ)        // 40960
#define NG 8
#define CORR_ELEMS ((size_t)NN * NG * SS * HWSZ)   // 10,485,760
#define MASK_ELEMS ((size_t)NN * SS * HWSZ)        // 1,310,720

// Scratch: normalized, channel-last (NHWC) copies of src/ref. 10 MB each.
__device__ float g_srcT[NPIX * CC];
__device__ float g_refT[NPIX * CC];

// ---------------------------------------------------------------------------
// Prepass: L2-normalize over channels and transpose NCHW -> NHWC.
// blockIdx.y = 0 -> ref, 1 -> src. 32 pixels per block, 256 threads.
// ---------------------------------------------------------------------------
__global__ __launch_bounds__(256) void norm_transpose_kernel(
    const float* __restrict__ ref, const float* __restrict__ src)
{
    const float* in  = blockIdx.y ? src : ref;
    float*       out = blockIdx.y ? g_srcT : g_refT;

    __shared__ float tile[32][CC + 1];   // +1 pad: avoid bank conflicts
    __shared__ float inv[32];

    int tid   = threadIdx.x;             // 0..255
    int pbase = blockIdx.x * 32;

    // Phase 1: coalesced load. tid = (cc, pp): pp fastest over pixels.
    {
        int pp = tid & 31;
        int cc = tid >> 5;               // 0..7
        int p  = pbase + pp;
        int n  = p / HWSZ;
        int hw = p - n * HWSZ;
        const float* base = in + (size_t)n * CC * HWSZ + hw;
#pragma unroll
        for (int it = 0; it < 8; it++) {
            int c = cc + it * 8;
            tile[pp][c] = base[(size_t)c * HWSZ];
        }
    }
    __syncthreads();

    // Phase 2: sum of squares per pixel; 8 threads per pixel.
    {
        int pp = tid >> 3;               // 0..31
        int k  = tid & 7;                // 0..7
        float s = 0.f;
#pragma unroll
        for (int j = 0; j < 8; j++) {
            float v = tile[pp][k * 8 + j];
            s += v * v;
        }
        s += __shfl_xor_sync(0xffffffffu, s, 1);
        s += __shfl_xor_sync(0xffffffffu, s, 2);
        s += __shfl_xor_sync(0xffffffffu, s, 4);
        if (k == 0) inv[pp] = 1.0f / (sqrtf(s) + 1e-9f);
    }
    __syncthreads();

    // Phase 3: coalesced NHWC write (channel fastest).
#pragma unroll
    for (int it = 0; it < 8; it++) {
        int idx = it * 256 + tid;        // 0..2047
        int pp  = idx >> 6;
        int c   = idx & 63;
        out[(size_t)(pbase + pp) * CC + c] = tile[pp][c] * inv[pp];
    }
}

// ---------------------------------------------------------------------------
// Main kernel: one warp per (n, h, w) output pixel; loops over S planes.
// Each lane owns 2 channels (float2). Bilinear gather of 4 corners from the
// NHWC src (each corner = one coalesced 256B warp load), blend, dot with
// register-resident ref channels, quad-shfl reduce to 8 group sums.
// ---------------------------------------------------------------------------
__global__ __launch_bounds__(256) void corr_kernel(
    const float* __restrict__ grids, float* __restrict__ out)
{
    int gw   = (blockIdx.x * blockDim.x + threadIdx.x) >> 5;  // global warp id
    int lane = threadIdx.x & 31;
    if (gw >= NPIX) return;

    int n  = gw / HWSZ;
    int hw = gw - n * HWSZ;

    // ref channels for this pixel: lanes hold channels 2*lane, 2*lane+1
    float2 r = *(const float2*)(g_refT + (size_t)gw * CC + lane * 2);

    // Preload grid coords for all 32 planes: lane s holds (gx, gy) for plane s.
    const float* gbase = grids + (size_t)n * SS * 2 * HWSZ + hw;
    float gxv = gbase[(size_t)(lane * 2 + 0) * HWSZ];
    float gyv = gbase[(size_t)(lane * 2 + 1) * HWSZ];

    const float* sb = g_srcT + (size_t)n * HWSZ * CC;
    float* corr_out = out;
    float* mask_out = out + CORR_ELEMS;
    int grp = lane >> 2;                 // group id 0..7 (lane quads)

#pragma unroll 4
    for (int s = 0; s < SS; s++) {
        float ix = __shfl_sync(0xffffffffu, gxv, s) - 0.5f;
        float iy = __shfl_sync(0xffffffffu, gyv, s) - 0.5f;

        float x0f = floorf(ix), y0f = floorf(iy);
        int   x0  = (int)x0f,   y0  = (int)y0f;
        float wx1 = ix - x0f,   wy1 = iy - y0f;
        float wx0 = 1.0f - wx1, wy0 = 1.0f - wy1;

        bool vx0 = (x0 >= 0) && (x0 <= WW - 1);
        bool vx1 = (x0 + 1 >= 0) && (x0 + 1 <= WW - 1);
        bool vy0 = (y0 >= 0) && (y0 <= HH - 1);
        bool vy1 = (y0 + 1 >= 0) && (y0 + 1 <= HH - 1);

        float w00 = wx0 * wy0, w10 = wx1 * wy0;
        float w01 = wx0 * wy1, w11 = wx1 * wy1;

        // Mask: numeric replication of grid_sample(ones) then threshold.
        float m = 0.f;
        m += (vx0 && vy0) ? w00 : 0.f;
        m += (vx1 && vy0) ? w10 : 0.f;
        m += (vx0 && vy1) ? w01 : 0.f;
        m += (vx1 && vy1) ? w11 : 0.f;
        float mask = (m < 0.9999f) ? 0.f : 1.f;

        // Bilinear blend over valid corners (conditions are warp-uniform).
        float2 acc = make_float2(0.f, 0.f);
        if (vy0) {
            const float* row = sb + (size_t)(y0 * WW) * CC + lane * 2;
            if (vx0) {
                float2 c = *(const float2*)(row + (size_t)x0 * CC);
                acc.x += w00 * c.x; acc.y += w00 * c.y;
            }
            if (vx1) {
                float2 c = *(const float2*)(row + (size_t)(x0 + 1) * CC);
                acc.x += w10 * c.x; acc.y += w10 * c.y;
            }
        }
        if (vy1) {
            const float* row = sb + (size_t)((y0 + 1) * WW) * CC + lane * 2;
            if (vx0) {
                float2 c = *(const float2*)(row + (size_t)x0 * CC);
                acc.x += w01 * c.x; acc.y += w01 * c.y;
            }
            if (vx1) {
                float2 c = *(const float2*)(row + (size_t)(x0 + 1) * CC);
                acc.x += w11 * c.x; acc.y += w11 * c.y;
            }
        }

        // Dot with ref channels; reduce lane quads -> group sums.
        float partial = acc.x * r.x + acc.y * r.y;
        partial += __shfl_xor_sync(0xffffffffu, partial, 1);
        partial += __shfl_xor_sync(0xffffffffu, partial, 2);
        partial *= mask;

        if ((lane & 3) == 0) {
            corr_out[(((size_t)n * NG + grp) * SS + s) * HWSZ + hw] = partial;
        }
        if (lane == 0) {
            mask_out[((size_t)n * SS + s) * HWSZ + hw] = mask;
        }
    }
}

extern "C" void kernel_launch(void* const* d_in, const int* in_sizes, int n_in,
                              void* d_out, int out_size)
{
    const float* feat_ref = (const float*)d_in[0];
    const float* feat_src = (const float*)d_in[1];
    const float* grids    = (const float*)d_in[2];
    (void)in_sizes; (void)n_in; (void)out_size;

    // Prepass: normalize + transpose both feature maps (gridDim.y selects which).
    dim3 pre_grid(NPIX / 32, 2);
    norm_transpose_kernel<<<pre_grid, 256>>>(feat_ref, feat_src);

    // Main: one warp per output pixel, 8 warps per block.
    corr_kernel<<<NPIX / 8, 256>>>(grids, (float*)d_out);
}

// round 3
// speedup vs baseline: 1.2243x; 1.2243x over previous
#include <cuda_runtime.h>
#include <cuda_fp16.h>
#include <math.h>

// PlanesweepCorrelation: N=2, C=64, S=32, H=128, W=160, G=8
#define NN 2
#define CC 64
#define SS 32
#define HH 128
#define WW 160
#define HWSZ (HH * WW)          // 20480
#define NPIX (NN * HWSZ)        // 40960
#define NG 8
#define CORR_ELEMS ((size_t)NN * NG * SS * HWSZ)   // 10,485,760
#define PIX_PER_BLK 16

// Scratch: normalized NHWC copies. src in fp16 (halves gather wavefronts),
// ref in fp32 (precision margin; read once per pixel).
__device__ __half g_srcT[NPIX * CC];
__device__ float  g_refT[NPIX * CC];

// ---------------------------------------------------------------------------
// Prepass: L2-normalize over channels, transpose NCHW -> NHWC.
// blockIdx.y = 0 -> ref (fp32 out), 1 -> src (fp16 out). 32 pixels / block.
// ---------------------------------------------------------------------------
__global__ __launch_bounds__(256) void norm_transpose_kernel(
    const float* __restrict__ ref, const float* __restrict__ src)
{
    const bool is_src = (blockIdx.y != 0);
    const float* in = is_src ? src : ref;

    __shared__ float tile[32][CC + 1];
    __shared__ float inv[32];

    int tid   = threadIdx.x;
    int pbase = blockIdx.x * 32;

    // coalesced NCHW load
    {
        int pp = tid & 31;
        int cc = tid >> 5;
        int p  = pbase + pp;
        int n  = p / HWSZ;
        int hw = p - n * HWSZ;
        const float* base = in + (size_t)n * CC * HWSZ + hw;
#pragma unroll
        for (int it = 0; it < 8; it++) {
            int c = cc + it * 8;
            tile[pp][c] = base[(size_t)c * HWSZ];
        }
    }
    __syncthreads();

    // per-pixel inverse norm (8 threads / pixel)
    {
        int pp = tid >> 3;
        int k  = tid & 7;
        float s = 0.f;
#pragma unroll
        for (int j = 0; j < 8; j++) {
            float v = tile[pp][k * 8 + j];
            s += v * v;
        }
        s += __shfl_xor_sync(0xffffffffu, s, 1);
        s += __shfl_xor_sync(0xffffffffu, s, 2);
        s += __shfl_xor_sync(0xffffffffu, s, 4);
        if (k == 0) inv[pp] = 1.0f / (sqrtf(s) + 1e-9f);
    }
    __syncthreads();

    // coalesced NHWC write
    if (is_src) {
#pragma unroll
        for (int it = 0; it < 8; it++) {
            int idx = it * 256 + tid;
            int pp  = idx >> 6;
            int c   = idx & 63;
            g_srcT[(size_t)(pbase + pp) * CC + c] =
                __float2half_rn(tile[pp][c] * inv[pp]);
        }
    } else {
#pragma unroll
        for (int it = 0; it < 8; it++) {
            int idx = it * 256 + tid;
            int pp  = idx >> 6;
            int c   = idx & 63;
            g_refT[(size_t)(pbase + pp) * CC + c] = tile[pp][c] * inv[pp];
        }
    }
}

// ---------------------------------------------------------------------------
// Main kernel. Block = 128 threads = 4 warps = 16 consecutive pixels
// (each warp handles 4 pixels sequentially). Per pixel:
//   prologue (lane = plane): bilinear weights/offsets/mask -> smem table
//   loop over 32 planes: 2 uniform LDS (table) + 4 fp16 corner loads (1 wf
//   each) + fp32 blend/dot + quad shfl-reduce -> smem staging
// Store phase: fully coalesced writes from smem staging.
// ---------------------------------------------------------------------------
__global__ __launch_bounds__(128) void corr_kernel(
    const float* __restrict__ grids, float* __restrict__ out)
{
    __shared__ float  s_c[PIX_PER_BLK * 257 + 16];   // [p*257 + s*8 + g]
    __shared__ float4 s_wA[PIX_PER_BLK][SS];         // weights
    __shared__ int4   s_oB[PIX_PER_BLK][SS];         // off, dx, dy, mask-bits
    __shared__ float  s_m[PIX_PER_BLK * 33];         // [p*33 + s]

    const int t    = threadIdx.x;
    const int w    = t >> 5;
    const int lane = t & 31;

    const int blkpix = blockIdx.x * PIX_PER_BLK;
    const int n      = blkpix / HWSZ;       // blocks never straddle n
    const int hw0    = blkpix - n * HWSZ;

    const float*  gb_n = grids + (size_t)n * (SS * 2) * HWSZ;
    const __half* sbl  = g_srcT + (size_t)n * HWSZ * CC + lane * 2;

    const int  grp = lane >> 2;
    const bool wr  = (lane & 3) == 0;

#pragma unroll
    for (int i = 0; i < 4; i++) {
        const int p  = w * 4 + i;
        const int hw = hw0 + p;

        // ref channels (fp32), lane owns channels 2*lane, 2*lane+1
        const float2 r = *(const float2*)(
            g_refT + ((size_t)n * HWSZ + hw) * CC + lane * 2);

        // ---- prologue: lane s computes plane-s scalars ----
        {
            const float gx = gb_n[(size_t)(2 * lane)     * HWSZ + hw];
            const float gy = gb_n[(size_t)(2 * lane + 1) * HWSZ + hw];
            float ixf = gx - 0.5f, iyf = gy - 0.5f;
            float x0f = floorf(ixf), y0f = floorf(iyf);
            int   x0 = (int)x0f,   y0 = (int)y0f;
            float wx1 = ixf - x0f, wy1 = iyf - y0f;
            float wx0 = 1.f - wx1, wy0 = 1.f - wy1;
            bool vx0 = (x0 >= 0)  && (x0 <  WW);
            bool vx1 = (x0 >= -1) && (x0 <  WW - 1);
            bool vy0 = (y0 >= 0)  && (y0 <  HH);
            bool vy1 = (y0 >= -1) && (y0 <  HH - 1);
            float w00 = (vx0 && vy0) ? wx0 * wy0 : 0.f;
            float w10 = (vx1 && vy0) ? wx1 * wy0 : 0.f;
            float w01 = (vx0 && vy1) ? wx0 * wy1 : 0.f;
            float w11 = (vx1 && vy1) ? wx1 * wy1 : 0.f;
            float msum = w00 + w10 + w01 + w11;
            float mask = (msum < 0.9999f) ? 0.f : 1.f;
            int xc0 = min(max(x0, 0),     WW - 1);
            int xc1 = min(max(x0 + 1, 0), WW - 1);
            int yc0 = min(max(y0, 0),     HH - 1);
            int yc1 = min(max(y0 + 1, 0), HH - 1);
            int off = (yc0 * WW + xc0) * (CC * 2);   // bytes (fp16 row = 128B)
            int dx  = (xc1 - xc0) * (CC * 2);
            int dy  = (yc1 - yc0) * (WW * CC * 2);
            s_wA[p][lane] = make_float4(w00, w10, w01, w11);
            s_oB[p][lane] = make_int4(off, dx, dy, __float_as_int(mask));
            s_m[p * 33 + lane] = mask;
        }
        __syncwarp();

        // ---- main loop over planes ----
        float* sc = s_c + p * 257;
#pragma unroll 4
        for (int s = 0; s < SS; s++) {
            float4 wv = s_wA[p][s];     // uniform -> broadcast LDS.128
            int4   ob = s_oB[p][s];     // uniform -> broadcast LDS.128
            const char* a = (const char*)sbl + ob.x;
            __half2 c00 = *(const __half2*)(a);
            __half2 c10 = *(const __half2*)(a + ob.y);
            __half2 c01 = *(const __half2*)(a + ob.z);
            __half2 c11 = *(const __half2*)(a + ob.y + ob.z);
            float2 f00 = __half22float2(c00), f10 = __half22float2(c10);
            float2 f01 = __half22float2(c01), f11 = __half22float2(c11);
            float ax = wv.x * f00.x + wv.y * f10.x + wv.z * f01.x + wv.w * f11.x;
            float ay = wv.x * f00.y + wv.y * f10.y + wv.z * f01.y + wv.w * f11.y;
            float partial = ax * r.x + ay * r.y;
            partial += __shfl_xor_sync(0xffffffffu, partial, 1);
            partial += __shfl_xor_sync(0xffffffffu, partial, 2);
            partial *= __int_as_float(ob.w);
            if (wr) sc[s * 8 + grp] = partial;
        }
        __syncwarp();
    }
    __syncthreads();

    // ---- store phase: coalesced ----
    {
        const int pl = t & 15;
        const int h  = t >> 4;          // 0..7
        float* po = out + (size_t)n * 256 * HWSZ + hw0 + pl;
#pragma unroll
        for (int i = 0; i < 32; i++) {
            int gs = i * 8 + h;         // gs = g*32 + s
            int s  = gs & 31;
            int g  = gs >> 5;
            po[(size_t)gs * HWSZ] = s_c[pl * 257 + s * 8 + g];
        }
        float* pm = out + CORR_ELEMS + (size_t)n * 32 * HWSZ + hw0 + pl;
#pragma unroll
        for (int i = 0; i < 4; i++) {
            int s = i * 8 + h;
            pm[(size_t)s * HWSZ] = s_m[pl * 33 + s];
        }
    }
}

extern "C" void kernel_launch(void* const* d_in, const int* in_sizes, int n_in,
                              void* d_out, int out_size)
{
    const float* feat_ref = (const float*)d_in[0];
    const float* feat_src = (const float*)d_in[1];
    const float* grids    = (const float*)d_in[2];
    (void)in_sizes; (void)n_in; (void)out_size;

    dim3 pre_grid(NPIX / 32, 2);
    norm_transpose_kernel<<<pre_grid, 256>>>(feat_ref, feat_src);

    corr_kernel<<<NPIX / PIX_PER_BLK, 128>>>(grids, (float*)d_out);
}

// round 4
// speedup vs baseline: 2.4879x; 2.0322x over previous
#include <cuda_runtime.h>
#include <cuda_fp16.h>
#include <math.h>

// PlanesweepCorrelation: N=2, C=64, S=32, H=128, W=160, G=8
#define NN 2
#define CC 64
#define SS 32
#define HH 128
#define WW 160
#define HWSZ (HH * WW)          // 20480
#define NPIX (NN * HWSZ)        // 40960
#define NG 8
#define CORR_ELEMS ((size_t)NN * NG * SS * HWSZ)   // 10,485,760
#define PIX_PER_BLK 8

// Normalized NHWC scratch. src fp16 (halves gather bytes), ref fp32.
__device__ __half g_srcT[NPIX * CC];
__device__ float  g_refT[NPIX * CC];

// ---------------------------------------------------------------------------
// Prepass: L2-normalize over channels, transpose NCHW -> NHWC.
// ---------------------------------------------------------------------------
__global__ __launch_bounds__(256) void norm_transpose_kernel(
    const float* __restrict__ ref, const float* __restrict__ src)
{
    const bool is_src = (blockIdx.y != 0);
    const float* in = is_src ? src : ref;

    __shared__ float tile[32][CC + 1];
    __shared__ float inv[32];

    int tid   = threadIdx.x;
    int pbase = blockIdx.x * 32;

    {
        int pp = tid & 31;
        int cc = tid >> 5;
        int p  = pbase + pp;
        int n  = p / HWSZ;
        int hw = p - n * HWSZ;
        const float* base = in + (size_t)n * CC * HWSZ + hw;
#pragma unroll
        for (int it = 0; it < 8; it++) {
            int c = cc + it * 8;
            tile[pp][c] = base[(size_t)c * HWSZ];
        }
    }
    __syncthreads();

    {
        int pp = tid >> 3;
        int k  = tid & 7;
        float s = 0.f;
#pragma unroll
        for (int j = 0; j < 8; j++) {
            float v = tile[pp][k * 8 + j];
            s += v * v;
        }
        s += __shfl_xor_sync(0xffffffffu, s, 1);
        s += __shfl_xor_sync(0xffffffffu, s, 2);
        s += __shfl_xor_sync(0xffffffffu, s, 4);
        if (k == 0) inv[pp] = 1.0f / (sqrtf(s) + 1e-9f);
    }
    __syncthreads();

    if (is_src) {
#pragma unroll
        for (int it = 0; it < 8; it++) {
            int idx = it * 256 + tid;
            int pp  = idx >> 6;
            int c   = idx & 63;
            g_srcT[(size_t)(pbase + pp) * CC + c] =
                __float2half_rn(tile[pp][c] * inv[pp]);
        }
    } else {
#pragma unroll
        for (int it = 0; it < 8; it++) {
            int idx = it * 256 + tid;
            int pp  = idx >> 6;
            int c   = idx & 63;
            g_refT[(size_t)(pbase + pp) * CC + c] = tile[pp][c] * inv[pp];
        }
    }
}

__device__ __forceinline__ float2 h2f(unsigned u) {
    return __half22float2(*reinterpret_cast<const __half2*>(&u));
}

// ---------------------------------------------------------------------------
// Main kernel. 128 threads = 4 warps; block covers 8 consecutive pixels
// (each warp handles 2). Octet layout: lane = (oct = plane sub-index, gl =
// channel group). 4 planes per warp iteration, no reduction shfls.
// ---------------------------------------------------------------------------
__global__ void __launch_bounds__(128, 8) corr_kernel(
    const float* __restrict__ grids, float* __restrict__ out)
{
    __shared__ float  s_g[2 * SS][PIX_PER_BLK + 1];  // staged grids [s*2+c][pp]
    __shared__ float4 s_w[PIX_PER_BLK][SS];          // mask-premult weights
    __shared__ int4   s_o[PIX_PER_BLK][SS];          // off, dx, dy, -
    __shared__ float  s_c[PIX_PER_BLK][SS * NG + 1]; // corr staging
    __shared__ float  s_m[PIX_PER_BLK][SS + 1];      // masks

    const int t    = threadIdx.x;
    const int w    = t >> 5;
    const int lane = t & 31;
    const int oct  = lane >> 3;      // 0..3: plane sub-index
    const int gl   = lane & 7;       // 0..7: channel group

    const int blkpix = blockIdx.x * PIX_PER_BLK;
    const int n      = blkpix / HWSZ;      // HWSZ % 8 == 0: no straddle
    const int hw0    = blkpix - n * HWSZ;

    // ---- cooperative grid staging (coalesced) ----
    const float* gb_n = grids + (size_t)n * (2 * SS) * HWSZ;
#pragma unroll
    for (int it = 0; it < 4; it++) {
        int idx = it * 128 + t;          // 0..511
        int sc  = idx >> 3;
        int pp  = idx & 7;
        s_g[sc][pp] = gb_n[(size_t)sc * HWSZ + hw0 + pp];
    }
    __syncthreads();

    const char* sb = (const char*)(g_srcT + (size_t)n * HWSZ * CC) + gl * 16;

#pragma unroll
    for (int pi = 0; pi < 2; pi++) {
        const int p  = w * 2 + pi;
        const int hw = hw0 + p;

        // ---- prologue: lane s computes plane-s table ----
        {
            const float gx = s_g[2 * lane][p];
            const float gy = s_g[2 * lane + 1][p];
            float ixf = gx - 0.5f, iyf = gy - 0.5f;
            float x0f = floorf(ixf), y0f = floorf(iyf);
            int   x0 = (int)x0f,   y0 = (int)y0f;
            float wx1 = ixf - x0f, wy1 = iyf - y0f;
            float wx0 = 1.f - wx1, wy0 = 1.f - wy1;
            bool vx0 = (x0 >= 0)  && (x0 <  WW);
            bool vx1 = (x0 >= -1) && (x0 <  WW - 1);
            bool vy0 = (y0 >= 0)  && (y0 <  HH);
            bool vy1 = (y0 >= -1) && (y0 <  HH - 1);
            float w00 = (vx0 && vy0) ? wx0 * wy0 : 0.f;
            float w10 = (vx1 && vy0) ? wx1 * wy0 : 0.f;
            float w01 = (vx0 && vy1) ? wx0 * wy1 : 0.f;
            float w11 = (vx1 && vy1) ? wx1 * wy1 : 0.f;
            float msum = w00 + w10 + w01 + w11;
            float mask = (msum < 0.9999f) ? 0.f : 1.f;
            int xc0 = min(max(x0, 0),     WW - 1);
            int xc1 = min(max(x0 + 1, 0), WW - 1);
            int yc0 = min(max(y0, 0),     HH - 1);
            int yc1 = min(max(y0 + 1, 0), HH - 1);
            int off = (yc0 * WW + xc0) * (CC * 2);   // bytes: fp16 row = 128B
            int dx  = (xc1 - xc0) * (CC * 2);
            int dy  = (yc1 - yc0) * (WW * CC * 2);
            s_w[p][lane] = make_float4(w00 * mask, w10 * mask,
                                       w01 * mask, w11 * mask);
            s_o[p][lane] = make_int4(off, dx, dy, 0);
            s_m[p][lane] = mask;
        }
        __syncwarp();

        // ref channels for group gl (fp32, 8 floats)
        const float4* rp = (const float4*)(
            g_refT + ((size_t)n * HWSZ + hw) * CC + gl * 8);
        const float4 rlo = rp[0];
        const float4 rhi = rp[1];

        float* scp = s_c[p];
#pragma unroll 2
        for (int it = 0; it < 8; it++) {
            const int s = it * 4 + oct;
            const float4 wv = s_w[p][s];     // broadcast LDS.128
            const int4   ob = s_o[p][s];     // broadcast LDS.128
            const char* a = sb + ob.x;
            uint4 c00 = *(const uint4*)(a);
            uint4 c10 = *(const uint4*)(a + ob.y);
            uint4 c01 = *(const uint4*)(a + ob.z);
            uint4 c11 = *(const uint4*)(a + ob.y + ob.z);

            float sum;
            {
                float2 f00 = h2f(c00.x), f10 = h2f(c10.x);
                float2 f01 = h2f(c01.x), f11 = h2f(c11.x);
                float bx = wv.x*f00.x + wv.y*f10.x + wv.z*f01.x + wv.w*f11.x;
                float by = wv.x*f00.y + wv.y*f10.y + wv.z*f01.y + wv.w*f11.y;
                sum = bx * rlo.x + by * rlo.y;
            }
            {
                float2 f00 = h2f(c00.y), f10 = h2f(c10.y);
                float2 f01 = h2f(c01.y), f11 = h2f(c11.y);
                float bx = wv.x*f00.x + wv.y*f10.x + wv.z*f01.x + wv.w*f11.x;
                float by = wv.x*f00.y + wv.y*f10.y + wv.z*f01.y + wv.w*f11.y;
                sum += bx * rlo.z + by * rlo.w;
            }
            {
                float2 f00 = h2f(c00.z), f10 = h2f(c10.z);
                float2 f01 = h2f(c01.z), f11 = h2f(c11.z);
                float bx = wv.x*f00.x + wv.y*f10.x + wv.z*f01.x + wv.w*f11.x;
                float by = wv.x*f00.y + wv.y*f10.y + wv.z*f01.y + wv.w*f11.y;
                sum += bx * rhi.x + by * rhi.y;
            }
            {
                float2 f00 = h2f(c00.w), f10 = h2f(c10.w);
                float2 f01 = h2f(c01.w), f11 = h2f(c11.w);
                float bx = wv.x*f00.x + wv.y*f10.x + wv.z*f01.x + wv.w*f11.x;
                float by = wv.x*f00.y + wv.y*f10.y + wv.z*f01.y + wv.w*f11.y;
                sum += bx * rhi.z + by * rhi.w;
            }
            scp[s * 8 + gl] = sum;          // 32 consecutive floats: 1 wf
        }
        __syncwarp();
    }
    __syncthreads();

    // ---- store phase: coalesced from smem staging ----
    {
        const int pl = t & 7;
        const int h  = t >> 3;           // 0..15
        float* po = out + (size_t)n * 256 * HWSZ + hw0 + pl;
#pragma unroll
        for (int i = 0; i < 16; i++) {
            int gs = i * 16 + h;         // gs = g*32 + s
            int s  = gs & 31;
            int g  = gs >> 5;
            po[(size_t)gs * HWSZ] = s_c[pl][s * 8 + g];
        }
        float* pm = out + CORR_ELEMS + (size_t)n * SS * HWSZ + hw0 + pl;
#pragma unroll
        for (int i = 0; i < 2; i++) {
            int s = i * 16 + h;
            pm[(size_t)s * HWSZ] = s_m[pl][s];
        }
    }
}

extern "C" void kernel_launch(void* const* d_in, const int* in_sizes, int n_in,
                              void* d_out, int out_size)
{
    const float* feat_ref = (const float*)d_in[0];
    const float* feat_src = (const float*)d_in[1];
    const float* grids    = (const float*)d_in[2];
    (void)in_sizes; (void)n_in; (void)out_size;

    dim3 pre_grid(NPIX / 32, 2);
    norm_transpose_kernel<<<pre_grid, 256>>>(feat_ref, feat_src);

    corr_kernel<<<NPIX / PIX_PER_BLK, 128>>>(grids, (float*)d_out);
}

// round 5
// speedup vs baseline: 2.7380x; 1.1005x over previous
#include <cuda_runtime.h>
#include <cuda_fp16.h>
#include <math.h>

// PlanesweepCorrelation: N=2, C=64, S=32, H=128, W=160, G=8
#define NN 2
#define CC 64
#define SS 32
#define HH 128
#define WW 160
#define HWSZ (HH * WW)          // 20480
#define NPIX (NN * HWSZ)        // 40960
#define NG 8
#define CORR_ELEMS ((size_t)NN * NG * SS * HWSZ)   // 10,485,760
#define PIX_PER_BLK 16

// Normalized NHWC scratch. src fp16 (halves gather bytes), ref fp32.
__device__ __half g_srcT[NPIX * CC];
__device__ float  g_refT[NPIX * CC];

// ---------------------------------------------------------------------------
// Prepass: L2-normalize over channels, transpose NCHW -> NHWC.
// ---------------------------------------------------------------------------
__global__ __launch_bounds__(256) void norm_transpose_kernel(
    const float* __restrict__ ref, const float* __restrict__ src)
{
    const bool is_src = (blockIdx.y != 0);
    const float* in = is_src ? src : ref;

    __shared__ float tile[32][CC + 1];
    __shared__ float inv[32];

    int tid   = threadIdx.x;
    int pbase = blockIdx.x * 32;

    {
        int pp = tid & 31;
        int cc = tid >> 5;
        int p  = pbase + pp;
        int n  = p / HWSZ;
        int hw = p - n * HWSZ;
        const float* base = in + (size_t)n * CC * HWSZ + hw;
#pragma unroll
        for (int it = 0; it < 8; it++) {
            int c = cc + it * 8;
            tile[pp][c] = base[(size_t)c * HWSZ];
        }
    }
    __syncthreads();

    {
        int pp = tid >> 3;
        int k  = tid & 7;
        float s = 0.f;
#pragma unroll
        for (int j = 0; j < 8; j++) {
            float v = tile[pp][k * 8 + j];
            s += v * v;
        }
        s += __shfl_xor_sync(0xffffffffu, s, 1);
        s += __shfl_xor_sync(0xffffffffu, s, 2);
        s += __shfl_xor_sync(0xffffffffu, s, 4);
        if (k == 0) inv[pp] = 1.0f / (sqrtf(s) + 1e-9f);
    }
    __syncthreads();

    if (is_src) {
#pragma unroll
        for (int it = 0; it < 8; it++) {
            int idx = it * 256 + tid;
            int pp  = idx >> 6;
            int c   = idx & 63;
            g_srcT[(size_t)(pbase + pp) * CC + c] =
                __float2half_rn(tile[pp][c] * inv[pp]);
        }
    } else {
#pragma unroll
        for (int it = 0; it < 8; it++) {
            int idx = it * 256 + tid;
            int pp  = idx >> 6;
            int c   = idx & 63;
            g_refT[(size_t)(pbase + pp) * CC + c] = tile[pp][c] * inv[pp];
        }
    }
}

__device__ __forceinline__ __half2 u2h2(unsigned u) {
    return *reinterpret_cast<const __half2*>(&u);
}

// ---------------------------------------------------------------------------
// Main kernel. 256 threads = 8 warps; block covers 16 consecutive pixels
// (each warp handles 2). Octet layout: lane = (oct = plane sub-index, gl =
// channel group). 4 planes per warp iteration, no reduction shfls.
// Blend in HFMA2 on fp16 corners; convert blended result; dot in fp32.
// ---------------------------------------------------------------------------
__global__ void __launch_bounds__(256, 4) corr_kernel(
    const float* __restrict__ grids, float* __restrict__ out)
{
    __shared__ float s_g[2 * SS][PIX_PER_BLK + 1];   // staged grids
    __shared__ int4  s_t[PIX_PER_BLK][SS];           // {w2lo, w2hi, off, dxdy}
    __shared__ float s_c[PIX_PER_BLK][SS * NG + 1];  // corr staging
    __shared__ float s_m[PIX_PER_BLK][SS + 1];       // masks

    const int t    = threadIdx.x;
    const int w    = t >> 5;
    const int lane = t & 31;
    const int oct  = lane >> 3;      // 0..3: plane sub-index
    const int gl   = lane & 7;       // 0..7: channel group

    const int blkpix = blockIdx.x * PIX_PER_BLK;
    const int n      = blkpix / HWSZ;      // HWSZ % 16 == 0: no straddle
    const int hw0    = blkpix - n * HWSZ;

    // ---- cooperative grid staging (coalesced) ----
    const float* gb_n = grids + (size_t)n * (2 * SS) * HWSZ;
#pragma unroll
    for (int it = 0; it < 4; it++) {
        int idx = it * 256 + t;          // 0..1023
        int sc  = idx >> 4;
        int pp  = idx & 15;
        s_g[sc][pp] = gb_n[(size_t)sc * HWSZ + hw0 + pp];
    }
    __syncthreads();

    const char* sb = (const char*)(g_srcT + (size_t)n * HWSZ * CC) + gl * 16;

#pragma unroll
    for (int pi = 0; pi < 2; pi++) {
        const int p  = w * 2 + pi;
        const int hw = hw0 + p;

        // ---- prologue: lane s computes plane-s table ----
        {
            const float gx = s_g[2 * lane][p];
            const float gy = s_g[2 * lane + 1][p];
            float ixf = gx - 0.5f, iyf = gy - 0.5f;
            float x0f = floorf(ixf), y0f = floorf(iyf);
            int   x0 = (int)x0f,   y0 = (int)y0f;
            float wx1 = ixf - x0f, wy1 = iyf - y0f;
            float wx0 = 1.f - wx1, wy0 = 1.f - wy1;
            bool vx0 = (x0 >= 0)  && (x0 <  WW);
            bool vx1 = (x0 >= -1) && (x0 <  WW - 1);
            bool vy0 = (y0 >= 0)  && (y0 <  HH);
            bool vy1 = (y0 >= -1) && (y0 <  HH - 1);
            float w00 = (vx0 && vy0) ? wx0 * wy0 : 0.f;
            float w10 = (vx1 && vy0) ? wx1 * wy0 : 0.f;
            float w01 = (vx0 && vy1) ? wx0 * wy1 : 0.f;
            float w11 = (vx1 && vy1) ? wx1 * wy1 : 0.f;
            float msum = w00 + w10 + w01 + w11;
            float mask = (msum < 0.9999f) ? 0.f : 1.f;
            int xc0 = min(max(x0, 0),     WW - 1);
            int xc1 = min(max(x0 + 1, 0), WW - 1);
            int yc0 = min(max(y0, 0),     HH - 1);
            int yc1 = min(max(y0 + 1, 0), HH - 1);
            int off = (yc0 * WW + xc0) * (CC * 2);   // bytes: fp16 row = 128B
            int dx  = (xc1 - xc0) * (CC * 2);        // 0 or 128
            int dy  = (yc1 - yc0) * (WW * CC * 2);   // 0 or 20480
            __half2 wlo = __floats2half2_rn(w00 * mask, w10 * mask);
            __half2 whi = __floats2half2_rn(w01 * mask, w11 * mask);
            int4 rec;
            rec.x = *reinterpret_cast<const int*>(&wlo);
            rec.y = *reinterpret_cast<const int*>(&whi);
            rec.z = off;
            rec.w = dx | (dy << 16);
            s_t[p][lane] = rec;
            s_m[p][lane] = mask;
        }
        __syncwarp();

        // ref channels for group gl (fp32, 8 floats)
        const float4* rp = (const float4*)(
            g_refT + ((size_t)n * HWSZ + hw) * CC + gl * 8);
        const float4 rlo = rp[0];
        const float4 rhi = rp[1];

        float* scp = s_c[p];
#pragma unroll 2
        for (int it = 0; it < 8; it++) {
            const int s = it * 4 + oct;
            const int4 rec = s_t[p][s];      // broadcast LDS.128 per octet
            const __half2 wp0 = u2h2((unsigned)rec.x);   // (w00, w10)
            const __half2 wp1 = u2h2((unsigned)rec.y);   // (w01, w11)
            const __half2 w00s = __low2half2(wp0);
            const __half2 w10s = __high2half2(wp0);
            const __half2 w01s = __low2half2(wp1);
            const __half2 w11s = __high2half2(wp1);
            const int dx = rec.w & 0xffff;
            const int dy = rec.w >> 16;

            const char* a = sb + rec.z;
            uint4 c00 = *(const uint4*)(a);
            uint4 c10 = *(const uint4*)(a + dx);
            uint4 c01 = *(const uint4*)(a + dy);
            uint4 c11 = *(const uint4*)(a + dx + dy);

            // fp16 bilinear blend (mask folded into weights)
            __half2 a0 = __hmul2(w00s, u2h2(c00.x));
            __half2 a1 = __hmul2(w00s, u2h2(c00.y));
            __half2 a2 = __hmul2(w00s, u2h2(c00.z));
            __half2 a3 = __hmul2(w00s, u2h2(c00.w));
            a0 = __hfma2(w10s, u2h2(c10.x), a0);
            a1 = __hfma2(w10s, u2h2(c10.y), a1);
            a2 = __hfma2(w10s, u2h2(c10.z), a2);
            a3 = __hfma2(w10s, u2h2(c10.w), a3);
            a0 = __hfma2(w01s, u2h2(c01.x), a0);
            a1 = __hfma2(w01s, u2h2(c01.y), a1);
            a2 = __hfma2(w01s, u2h2(c01.z), a2);
            a3 = __hfma2(w01s, u2h2(c01.w), a3);
            a0 = __hfma2(w11s, u2h2(c11.x), a0);
            a1 = __hfma2(w11s, u2h2(c11.y), a1);
            a2 = __hfma2(w11s, u2h2(c11.z), a2);
            a3 = __hfma2(w11s, u2h2(c11.w), a3);

            // convert blended pairs, dot with fp32 ref
            float2 f0 = __half22float2(a0);
            float2 f1 = __half22float2(a1);
            float2 f2 = __half22float2(a2);
            float2 f3 = __half22float2(a3);
            float sum = f0.x * rlo.x + f0.y * rlo.y
                      + f1.x * rlo.z + f1.y * rlo.w
                      + f2.x * rhi.x + f2.y * rhi.y
                      + f3.x * rhi.z + f3.y * rhi.w;

            scp[s * 8 + gl] = sum;           // 32 consecutive floats: 1 wf
        }
        __syncwarp();
    }
    __syncthreads();

    // ---- store phase: coalesced from smem staging ----
    {
        const int pl = t & 15;           // pixel
        const int h  = t >> 4;           // 0..15
        float* po = out + (size_t)n * 256 * HWSZ + hw0 + pl;
#pragma unroll
        for (int i = 0; i < 16; i++) {
            int gs = i * 16 + h;         // gs = g*32 + s
            int s  = gs & 31;
            int g  = gs >> 5;
            po[(size_t)gs * HWSZ] = s_c[pl][s * 8 + g];
        }
        float* pm = out + CORR_ELEMS + (size_t)n * SS * HWSZ + hw0 + pl;
#pragma unroll
        for (int i = 0; i < 2; i++) {
            int s = i * 16 + h;
            pm[(size_t)s * HWSZ] = s_m[pl][s];
        }
    }
}

extern "C" void kernel_launch(void* const* d_in, const int* in_sizes, int n_in,
                              void* d_out, int out_size)
{
    const float* feat_ref = (const float*)d_in[0];
    const float* feat_src = (const float*)d_in[1];
    const float* grids    = (const float*)d_in[2];
    (void)in_sizes; (void)n_in; (void)out_size;

    dim3 pre_grid(NPIX / 32, 2);
    norm_transpose_kernel<<<pre_grid, 256>>>(feat_ref, feat_src);

    corr_kernel<<<NPIX / PIX_PER_BLK, 256>>>(grids, (float*)d_out);
}

// round 6
// speedup vs baseline: 2.8324x; 1.0345x over previous
#include <cuda_runtime.h>
#include <cuda_fp16.h>
#include <math.h>

// PlanesweepCorrelation: N=2, C=64, S=32, H=128, W=160, G=8
#define NN 2
#define CC 64
#define SS 32
#define HH 128
#define WW 160
#define HWSZ (HH * WW)          // 20480
#define NPIX (NN * HWSZ)        // 40960
#define NG 8
#define CORR_ELEMS ((size_t)NN * NG * SS * HWSZ)   // 10,485,760
#define PIX_PER_BLK 16

// Normalized NHWC scratch. src fp16 (halves gather bytes), ref fp32.
__device__ __half g_srcT[NPIX * CC];
__device__ float  g_refT[NPIX * CC];

// ---------------------------------------------------------------------------
// Prepass: L2-normalize over channels, transpose NCHW -> NHWC.
// ---------------------------------------------------------------------------
__global__ __launch_bounds__(256) void norm_transpose_kernel(
    const float* __restrict__ ref, const float* __restrict__ src)
{
    const bool is_src = (blockIdx.y != 0);
    const float* in = is_src ? src : ref;

    __shared__ float tile[32][CC + 1];
    __shared__ float inv[32];

    int tid   = threadIdx.x;
    int pbase = blockIdx.x * 32;

    {
        int pp = tid & 31;
        int cc = tid >> 5;
        int p  = pbase + pp;
        int n  = p / HWSZ;
        int hw = p - n * HWSZ;
        const float* base = in + (size_t)n * CC * HWSZ + hw;
#pragma unroll
        for (int it = 0; it < 8; it++) {
            int c = cc + it * 8;
            tile[pp][c] = base[(size_t)c * HWSZ];
        }
    }
    __syncthreads();

    {
        int pp = tid >> 3;
        int k  = tid & 7;
        float s = 0.f;
#pragma unroll
        for (int j = 0; j < 8; j++) {
            float v = tile[pp][k * 8 + j];
            s += v * v;
        }
        s += __shfl_xor_sync(0xffffffffu, s, 1);
        s += __shfl_xor_sync(0xffffffffu, s, 2);
        s += __shfl_xor_sync(0xffffffffu, s, 4);
        if (k == 0) inv[pp] = 1.0f / (sqrtf(s) + 1e-9f);
    }
    __syncthreads();

    if (is_src) {
#pragma unroll
        for (int it = 0; it < 8; it++) {
            int idx = it * 256 + tid;
            int pp  = idx >> 6;
            int c   = idx & 63;
            g_srcT[(size_t)(pbase + pp) * CC + c] =
                __float2half_rn(tile[pp][c] * inv[pp]);
        }
    } else {
#pragma unroll
        for (int it = 0; it < 8; it++) {
            int idx = it * 256 + tid;
            int pp  = idx >> 6;
            int c   = idx & 63;
            g_refT[(size_t)(pbase + pp) * CC + c] = tile[pp][c] * inv[pp];
        }
    }
}

__device__ __forceinline__ __half2 u2h2(unsigned u) {
    return *reinterpret_cast<const __half2*>(&u);
}

// ---------------------------------------------------------------------------
// Main kernel. 256 threads = 8 warps; block covers 16 consecutive pixels
// (each warp handles 2). Octet layout: lane = (oct = plane sub-index, gl =
// channel group). 4 planes per warp iteration, no reduction shfls.
// HFMA2 blend on fp16 corners; fp32 dot with ref. Table record for the next
// iteration is prefetched (software pipeline) to hide the LDS->LDG chain.
// ---------------------------------------------------------------------------
__global__ void __launch_bounds__(256, 5) corr_kernel(
    const float* __restrict__ grids, float* __restrict__ out)
{
    __shared__ float s_g[2 * SS][PIX_PER_BLK + 1];   // staged grids
    __shared__ int4  s_t[PIX_PER_BLK][SS];           // {w2lo, w2hi, off, dxdy}
    __shared__ float s_c[PIX_PER_BLK][SS * NG + 1];  // corr staging
    __shared__ float s_m[PIX_PER_BLK][SS + 1];       // masks

    const int t    = threadIdx.x;
    const int w    = t >> 5;
    const int lane = t & 31;
    const int oct  = lane >> 3;      // 0..3: plane sub-index
    const int gl   = lane & 7;       // 0..7: channel group

    const int blkpix = blockIdx.x * PIX_PER_BLK;
    const int n      = blkpix / HWSZ;      // HWSZ % 16 == 0: no straddle
    const int hw0    = blkpix - n * HWSZ;

    // ---- cooperative grid staging (coalesced) ----
    const float* gb_n = grids + (size_t)n * (2 * SS) * HWSZ;
#pragma unroll
    for (int it = 0; it < 4; it++) {
        int idx = it * 256 + t;          // 0..1023
        int sc  = idx >> 4;
        int pp  = idx & 15;
        s_g[sc][pp] = gb_n[(size_t)sc * HWSZ + hw0 + pp];
    }
    __syncthreads();

    const char* sb = (const char*)(g_srcT + (size_t)n * HWSZ * CC) + gl * 16;

#pragma unroll
    for (int pi = 0; pi < 2; pi++) {
        const int p  = w * 2 + pi;
        const int hw = hw0 + p;

        // ---- prologue: lane s computes plane-s table ----
        {
            const float gx = s_g[2 * lane][p];
            const float gy = s_g[2 * lane + 1][p];
            float ixf = gx - 0.5f, iyf = gy - 0.5f;
            float x0f = floorf(ixf), y0f = floorf(iyf);
            int   x0 = (int)x0f,   y0 = (int)y0f;
            float wx1 = ixf - x0f, wy1 = iyf - y0f;
            float wx0 = 1.f - wx1, wy0 = 1.f - wy1;
            bool vx0 = (x0 >= 0)  && (x0 <  WW);
            bool vx1 = (x0 >= -1) && (x0 <  WW - 1);
            bool vy0 = (y0 >= 0)  && (y0 <  HH);
            bool vy1 = (y0 >= -1) && (y0 <  HH - 1);
            float w00 = (vx0 && vy0) ? wx0 * wy0 : 0.f;
            float w10 = (vx1 && vy0) ? wx1 * wy0 : 0.f;
            float w01 = (vx0 && vy1) ? wx0 * wy1 : 0.f;
            float w11 = (vx1 && vy1) ? wx1 * wy1 : 0.f;
            float msum = w00 + w10 + w01 + w11;
            float mask = (msum < 0.9999f) ? 0.f : 1.f;
            int xc0 = min(max(x0, 0),     WW - 1);
            int xc1 = min(max(x0 + 1, 0), WW - 1);
            int yc0 = min(max(y0, 0),     HH - 1);
            int yc1 = min(max(y0 + 1, 0), HH - 1);
            int off = (yc0 * WW + xc0) * (CC * 2);   // bytes: fp16 row = 128B
            int dx  = (xc1 - xc0) * (CC * 2);        // 0 or 128
            int dy  = (yc1 - yc0) * (WW * CC * 2);   // 0 or 20480
            __half2 wlo = __floats2half2_rn(w00 * mask, w10 * mask);
            __half2 whi = __floats2half2_rn(w01 * mask, w11 * mask);
            int4 rec;
            rec.x = *reinterpret_cast<const int*>(&wlo);
            rec.y = *reinterpret_cast<const int*>(&whi);
            rec.z = off;
            rec.w = dx | (dy << 16);
            s_t[p][lane] = rec;
            s_m[p][lane] = mask;
        }
        __syncwarp();

        // ref channels for group gl (fp32, 8 floats)
        const float4* rp = (const float4*)(
            g_refT + ((size_t)n * HWSZ + hw) * CC + gl * 8);
        const float4 rlo = rp[0];
        const float4 rhi = rp[1];

        float* scp = s_c[p];

        // ---- main loop: 4 planes/iter, next table record prefetched ----
        int4 rec = s_t[p][oct];              // it = 0
#pragma unroll 2
        for (int it = 0; it < 8; it++) {
            const int4 cur = rec;
            rec = s_t[p][(((it + 1) & 7) << 2) + oct];   // prefetch next

            const int s = (it << 2) + oct;
            const __half2 wp0 = u2h2((unsigned)cur.x);   // (w00, w10)
            const __half2 wp1 = u2h2((unsigned)cur.y);   // (w01, w11)
            const __half2 w00s = __low2half2(wp0);
            const __half2 w10s = __high2half2(wp0);
            const __half2 w01s = __low2half2(wp1);
            const __half2 w11s = __high2half2(wp1);
            const int dx = cur.w & 0xffff;
            const int dy = cur.w >> 16;

            const char* a = sb + cur.z;
            uint4 c00 = *(const uint4*)(a);
            uint4 c10 = *(const uint4*)(a + dx);
            uint4 c01 = *(const uint4*)(a + dy);
            uint4 c11 = *(const uint4*)(a + dx + dy);

            // fp16 bilinear blend (mask folded into weights)
            __half2 a0 = __hmul2(w00s, u2h2(c00.x));
            __half2 a1 = __hmul2(w00s, u2h2(c00.y));
            __half2 a2 = __hmul2(w00s, u2h2(c00.z));
            __half2 a3 = __hmul2(w00s, u2h2(c00.w));
            a0 = __hfma2(w10s, u2h2(c10.x), a0);
            a1 = __hfma2(w10s, u2h2(c10.y), a1);
            a2 = __hfma2(w10s, u2h2(c10.z), a2);
            a3 = __hfma2(w10s, u2h2(c10.w), a3);
            a0 = __hfma2(w01s, u2h2(c01.x), a0);
            a1 = __hfma2(w01s, u2h2(c01.y), a1);
            a2 = __hfma2(w01s, u2h2(c01.z), a2);
            a3 = __hfma2(w01s, u2h2(c01.w), a3);
            a0 = __hfma2(w11s, u2h2(c11.x), a0);
            a1 = __hfma2(w11s, u2h2(c11.y), a1);
            a2 = __hfma2(w11s, u2h2(c11.z), a2);
            a3 = __hfma2(w11s, u2h2(c11.w), a3);

            // convert blended pairs, dot with fp32 ref
            float2 f0 = __half22float2(a0);
            float2 f1 = __half22float2(a1);
            float2 f2 = __half22float2(a2);
            float2 f3 = __half22float2(a3);
            float sum = f0.x * rlo.x + f0.y * rlo.y
                      + f1.x * rlo.z + f1.y * rlo.w
                      + f2.x * rhi.x + f2.y * rhi.y
                      + f3.x * rhi.z + f3.y * rhi.w;

            scp[(s << 3) + gl] = sum;        // 32 consecutive floats: 1 wf
        }
        __syncwarp();
    }
    __syncthreads();

    // ---- store phase: coalesced from smem staging ----
    {
        const int pl = t & 15;           // pixel
        const int h  = t >> 4;           // 0..15
        float* po = out + (size_t)n * 256 * HWSZ + hw0 + pl;
#pragma unroll
        for (int i = 0; i < 16; i++) {
            int gs = i * 16 + h;         // gs = g*32 + s
            int s  = gs & 31;
            int g  = gs >> 5;
            po[(size_t)gs * HWSZ] = s_c[pl][s * 8 + g];
        }
        float* pm = out + CORR_ELEMS + (size_t)n * SS * HWSZ + hw0 + pl;
#pragma unroll
        for (int i = 0; i < 2; i++) {
            int s = i * 16 + h;
            pm[(size_t)s * HWSZ] = s_m[pl][s];
        }
    }
}

extern "C" void kernel_launch(void* const* d_in, const int* in_sizes, int n_in,
                              void* d_out, int out_size)
{
    const float* feat_ref = (const float*)d_in[0];
    const float* feat_src = (const float*)d_in[1];
    const float* grids    = (const float*)d_in[2];
    (void)in_sizes; (void)n_in; (void)out_size;

    dim3 pre_grid(NPIX / 32, 2);
    norm_transpose_kernel<<<pre_grid, 256>>>(feat_ref, feat_src);

    corr_kernel<<<NPIX / PIX_PER_BLK, 256>>>(grids, (float*)d_out);
}